// round 9
// baseline (speedup 1.0000x reference)
#include <cuda_runtime.h>
#include <math.h>
#include <stddef.h>
#include <stdint.h>

#define B_ 256
#define W_ 512
#define F_ 512
#define N_ 512
#define WT 16                 // words per tile (== #warps)
#define NT (W_ / WT)          // 32 tiles
#define NB 256                // grid size (must all be resident!)

// Scratch (device globals — no allocation allowed)
__device__ float g_t  [B_*F_];   // t   = sum_w w[w]*x[b,w,:]
__device__ float g_Mqk[F_*F_];   // Mqk = (wq @ wk^T) * rsqrt(N)
__device__ float g_qk [B_*F_];   // qk  = t @ Mqk
__device__ float g_y  [B_*F_];   // y   = sum_w softmax_w * x[b,w,:]

// Grid barrier state (monotonic across graph replays)
__device__ unsigned g_arrive = 0;
__device__ volatile unsigned g_release = 0;

__device__ __forceinline__ void grid_sync() {
    __syncthreads();
    if (threadIdx.x == 0) {
        __threadfence();                                  // publish this CTA's writes
        unsigned t = atomicAdd(&g_arrive, 1u) + 1u;       // 1-based arrival ticket
        unsigned gen = (t - 1u) / NB + 1u;                // generation of this barrier
        if (t == gen * NB) {
            g_release = gen;                              // last arriver releases
            __threadfence();
        } else {
            while (g_release < gen) { __nanosleep(64); }
            __threadfence();                              // acquire
        }
    }
    __syncthreads();
}

// ---------------------------------------------------------------------------
// cp.async helpers
// ---------------------------------------------------------------------------
__device__ __forceinline__ void cp_async16(void* dst_smem, const void* src_gmem) {
    uint32_t d = (uint32_t)__cvta_generic_to_shared(dst_smem);
    asm volatile("cp.async.cg.shared.global [%0], [%1], 16;\n" :: "r"(d), "l"(src_gmem));
}
__device__ __forceinline__ void cp_commit() {
    asm volatile("cp.async.commit_group;\n");
}
template <int Nw>
__device__ __forceinline__ void cp_wait() {
    asm volatile("cp.async.wait_group %0;\n" :: "n"(Nw));
}

// Issue one WT x F_ tile (2048 float4) into smem buffer; 4 cp.async/thread.
__device__ __forceinline__ void issue_tile(float* dst, const float4* xb4,
                                           int t0, int tid) {
    #pragma unroll
    for (int j = 0; j < 4; j++) {
        int e = tid + j * 512;               // 0..2047
        int w = e >> 7, f4 = e & 127;
        cp_async16(&dst[w * F_ + f4 * 4], &xb4[(size_t)(t0 + w) * 128 + f4]);
    }
    cp_commit();
}

// ---------------------------------------------------------------------------
// 32x32 GEMM tile with 512 threads, BK=32.
// C[m0:+32, n0:+32] = A[m0:+32, :512] @ (TRANS_B ? Bm^T : Bm) * scale
// All matrices 512-wide row-major (A rows stride 512, C stride 512).
// Per thread: m = tid>>4 (one row), n pair = (tid&15)*2.
// ---------------------------------------------------------------------------
template <int TRANS_B>
__device__ void gemm_tile512(const float* __restrict__ A,
                             const float* __restrict__ Bm,
                             float* __restrict__ C,
                             int m0, int n0, float scale, float* sm) {
    float (*As)[36] = (float(*)[36])sm;              // [32][36]
    float (*Bs)[36] = (float(*)[36])(sm + 32 * 36);  // [32][36]
    const int tid = threadIdx.x;
    const int lr  = tid >> 4;          // 0..31
    const int lc2 = (tid & 15) * 2;    // 0,2,..,30
    float c0 = 0.f, c1 = 0.f;

    for (int k0 = 0; k0 < 512; k0 += 32) {
        const float2 av = *(const float2*)&A[(size_t)(m0 + lr) * 512 + k0 + lc2];
        float2 bv;
        if (TRANS_B) bv = *(const float2*)&Bm[(size_t)(n0 + lr) * 512 + k0 + lc2];
        else         bv = *(const float2*)&Bm[(size_t)(k0 + lr) * 512 + n0 + lc2];
        __syncthreads();               // previous iter finished reading tiles
        As[lc2][lr] = av.x; As[lc2 + 1][lr] = av.y;
        if (TRANS_B) { Bs[lc2][lr] = bv.x; Bs[lc2 + 1][lr] = bv.y; }
        else         { *(float2*)&Bs[lr][lc2] = bv; }
        __syncthreads();
        #pragma unroll
        for (int k = 0; k < 32; k++) {
            const float a = As[k][lr];
            const float2 b = *(const float2*)&Bs[k][lc2];
            c0 += a * b.x; c1 += a * b.y;
        }
    }
    C[(size_t)(m0 + lr) * 512 + n0 + lc2]     = c0 * scale;
    C[(size_t)(m0 + lr) * 512 + n0 + lc2 + 1] = c1 * scale;
}

// ---------------------------------------------------------------------------
// Pass A body: t[b][f] for two batches (cta 0..127 -> batches 2c, 2c+1).
// R8-proven schedule: issue next -> wait<1> -> compute, descending tiles.
// ---------------------------------------------------------------------------
__device__ void passA(float* sm, const float* __restrict__ x,
                      const float* __restrict__ wvec, int cta) {
    float* ws   = sm;
    float* bufs[2] = { sm + F_, sm + F_ + WT * F_ };
    const int tid = threadIdx.x;
    ws[tid] = wvec[tid];

    for (int bb = 0; bb < 2; bb++) {
        const int b = cta * 2 + bb;
        const float4* xb4 = (const float4*)(x + (size_t)b * W_ * F_);
        issue_tile(bufs[0], xb4, (NT - 1) * WT, tid);
        __syncthreads();                         // ws visible / prev batch done

        float acc = 0.f;
        for (int i = 0; i < NT; i++) {
            const int t = NT - 1 - i;            // descending
            const int cur = i & 1, nxt = cur ^ 1;
            if (i < NT - 1) {
                issue_tile(bufs[nxt], xb4, (t - 1) * WT, tid);
                cp_wait<1>();
            } else {
                cp_wait<0>();
            }
            __syncthreads();                     // tile cur ready

            const float* xt  = bufs[cur];
            const float* wst = ws + t * WT;
            #pragma unroll
            for (int w = 0; w < WT; w++)
                acc += wst[w] * xt[w * F_ + tid];
            __syncthreads();                     // done reading before re-issue
        }
        g_t[b * F_ + tid] = acc;
    }
}

// ---------------------------------------------------------------------------
// Pass B body: scores + online softmax + weighted accumulate for batch = cta.
// Exact R8 structure (52.5us standalone).
// ---------------------------------------------------------------------------
__device__ void passB(float* sm, const float* __restrict__ x, int b) {
    float* qks = sm;
    float* bufs[2] = { sm + F_, sm + F_ + WT * F_ };
    __shared__ float sc[WT];
    __shared__ float ps[WT];

    const int tid = threadIdx.x;
    const int wi = tid >> 5, lane = tid & 31;

    qks[tid] = g_qk[b * F_ + tid];
    const float4* xb4 = (const float4*)(x + (size_t)b * W_ * F_);

    issue_tile(bufs[0], xb4, 0, tid);
    __syncthreads();                             // qks visible

    float qkr[16];
    #pragma unroll
    for (int j = 0; j < 16; j++) qkr[j] = qks[lane + 32 * j];

    float m = -1e30f, s = 0.f, y = 0.f;

    for (int t = 0; t < NT; t++) {
        const int cur = t & 1, nxt = cur ^ 1;
        if (t < NT - 1) {
            issue_tile(bufs[nxt], xb4, (t + 1) * WT, tid);
            cp_wait<1>();
        } else {
            cp_wait<0>();
        }
        __syncthreads();                         // tile cur ready (guards sc reuse)

        float d = 0.f;
        const float* xw = &bufs[cur][wi * F_];
        #pragma unroll
        for (int j = 0; j < 16; j++) d += xw[lane + 32 * j] * qkr[j];
        #pragma unroll
        for (int o = 16; o > 0; o >>= 1) d += __shfl_xor_sync(0xffffffffu, d, o);
        if (lane == 0) sc[wi] = d;
        __syncthreads();                         // sc ready

        float mn = m;
        #pragma unroll
        for (int w = 0; w < WT; w++) mn = fmaxf(mn, sc[w]);
        const float corr = __expf(m - mn);
        if (tid < WT) ps[tid] = __expf(sc[tid] - mn);
        m = mn;
        __syncthreads();                         // ps ready

        float pr[WT];
        #pragma unroll
        for (int w = 0; w < WT; w++) pr[w] = ps[w];
        float psum = 0.f;
        #pragma unroll
        for (int w = 0; w < WT; w++) psum += pr[w];
        s = s * corr + psum;
        y *= corr;
        #pragma unroll
        for (int w = 0; w < WT; w++) y += pr[w] * bufs[cur][w * F_ + tid];
    }
    g_y[b * F_ + tid] = y / s;
}

// ---------------------------------------------------------------------------
// The single persistent kernel: 256 CTAs x 512 threads, 2 CTAs/SM guaranteed.
// ---------------------------------------------------------------------------
__global__ __launch_bounds__(512, 2) void k_all(const float* __restrict__ x,
                                                const float* __restrict__ wk,
                                                const float* __restrict__ wq,
                                                const float* __restrict__ wv,
                                                const float* __restrict__ wvec,
                                                float* __restrict__ out) {
    extern __shared__ float sm[];
    const int cta = blockIdx.x;
    const float rsqrtN = 0.04419417382415922f;   // 1/sqrt(512)

    // ---- P0: passA (CTAs 0..127) || Mqk GEMM (CTAs 128..255) ----
    if (cta < 128) {
        passA(sm, x, wvec, cta);
    } else {
        #pragma unroll
        for (int r = 0; r < 2; r++) {
            const int tile = (cta - 128) * 2 + r;        // 0..255 over 16x16 tiles
            gemm_tile512<1>(wq, wk, g_Mqk, (tile >> 4) * 32, (tile & 15) * 32,
                            rsqrtN, sm);
        }
    }
    grid_sync();

    // ---- P1: qk = T @ Mqk  (256x512, 8x16 = 128 tiles on CTAs 0..127) ----
    if (cta < 128) {
        gemm_tile512<0>(g_t, g_Mqk, g_qk, (cta >> 4) * 32, (cta & 15) * 32,
                        1.f, sm);
    }
    grid_sync();

    // ---- P2: passB (one batch per CTA) ----
    passB(sm, x, cta);
    grid_sync();

    // ---- P3: out = y @ wv  (128 tiles on CTAs 0..127) ----
    if (cta < 128) {
        gemm_tile512<0>(g_y, wv, out, (cta >> 4) * 32, (cta & 15) * 32,
                        1.f, sm);
    }
}

// ---------------------------------------------------------------------------
extern "C" void kernel_launch(void* const* d_in, const int* in_sizes, int n_in,
                              void* d_out, int out_size) {
    const float* x    = (const float*)d_in[0];
    const float* wk   = (const float*)d_in[1];
    const float* wq   = (const float*)d_in[2];
    const float* wv   = (const float*)d_in[3];
    const float* wvec = (const float*)d_in[4];
    float* out = (float*)d_out;

    const int pipe_smem = (F_ + 2 * WT * F_) * sizeof(float);   // 67584
    static int attr_set = 0;   // idempotent host-side attribute set (no device work)
    cudaFuncSetAttribute(k_all, cudaFuncAttributeMaxDynamicSharedMemorySize, pipe_smem);
    (void)attr_set;

    k_all<<<NB, 512, pipe_smem>>>(x, wk, wq, wv, wvec, out);
}

// round 10
// speedup vs baseline: 1.0994x; 1.0994x over previous
#include <cuda_runtime.h>
#include <math.h>
#include <stddef.h>
#include <stdint.h>

#define B_ 256
#define W_ 512
#define F_ 512
#define N_ 512
#define WT 16                 // words per tile (== #warps)
#define NT (W_ / WT)          // 32 tiles
#define NBUF 3
#define TILE_BYTES (WT * F_ * 4)   // 32768: one tile is a contiguous chunk of x[b]

// Scratch (device globals — no allocation allowed)
__device__ float g_t [B_*F_];   // t  = sum_w w[w]*x[b,w,:]
__device__ float g_q [B_*N_];   // Q  = t @ wq
__device__ float g_qk[B_*F_];   // qk = (Q @ wk^T) * rsqrt(N)
__device__ float g_y [B_*F_];   // y  = sum_w softmax_w * x[b,w,:]

// ---------------------------------------------------------------------------
// TMA bulk + mbarrier helpers
// ---------------------------------------------------------------------------
__device__ __forceinline__ uint32_t s2u(const void* p) {
    return (uint32_t)__cvta_generic_to_shared(p);
}
__device__ __forceinline__ void mbar_init(uint32_t a, uint32_t n) {
    asm volatile("mbarrier.init.shared.b64 [%0], %1;" :: "r"(a), "r"(n) : "memory");
}
__device__ __forceinline__ void fence_proxy_async_cta() {
    asm volatile("fence.proxy.async.shared::cta;" ::: "memory");
}
__device__ __forceinline__ void mbar_expect_tx(uint32_t a, uint32_t bytes) {
    asm volatile("mbarrier.arrive.expect_tx.shared.b64 _, [%0], %1;"
                 :: "r"(a), "r"(bytes) : "memory");
}
__device__ __forceinline__ void tma_1d(uint32_t dst, const void* src,
                                       uint32_t bytes, uint32_t mbar) {
    asm volatile(
        "cp.async.bulk.shared::cta.global.mbarrier::complete_tx::bytes "
        "[%0], [%1], %2, [%3];"
        :: "r"(dst), "l"(src), "r"(bytes), "r"(mbar) : "memory");
}
__device__ __forceinline__ void mbar_wait(uint32_t a, uint32_t parity) {
    asm volatile(
        "{\n\t.reg .pred P;\n"
        "W%=:\n\tmbarrier.try_wait.parity.acquire.cta.shared::cta.b64 P, [%0], %1, 0x989680;\n"
        "\t@P bra D%=;\n"
        "\tbra W%=;\n"
        "D%=:\n}"
        :: "r"(a), "r"(parity) : "memory");
}

// Elected-thread issue of one 32KB tile into a buffer
__device__ __forceinline__ void issue_tile_tma(float* dst, const char* xb,
                                               int tile, uint32_t mbar) {
    mbar_expect_tx(mbar, TILE_BYTES);
    tma_1d(s2u(dst), xb + (size_t)tile * TILE_BYTES, TILE_BYTES, mbar);
}

// ---------------------------------------------------------------------------
// Pass A: t[b][f] = sum_w w[w] * x[b][w][f]
// One CTA per batch, 512 threads, 2 CTAs/SM. TMA 3-buffer pipeline, tiles
// DESCENDING so pass B's start (w=0) is L2-warm.
// Dynamic smem: ws[512] | buf[3][WT*512]   (100352 B)
// ---------------------------------------------------------------------------
__global__ __launch_bounds__(512, 2) void k_t(const float* __restrict__ x,
                                              const float* __restrict__ wvec) {
    extern __shared__ float sm[];
    float* ws = sm;
    float* bufs[NBUF] = { sm + F_, sm + F_ + WT * F_, sm + F_ + 2 * WT * F_ };
    __shared__ alignas(8) unsigned long long mbar[NBUF];

    const int b = blockIdx.x, tid = threadIdx.x;
    const char* xb = (const char*)(x + (size_t)b * W_ * F_);

    if (tid == 0) {
        #pragma unroll
        for (int i = 0; i < NBUF; i++) mbar_init(s2u(&mbar[i]), 1);
        fence_proxy_async_cta();
    }
    ws[tid] = wvec[tid];
    __syncthreads();                         // init + ws visible

    if (tid == 0) {
        #pragma unroll
        for (int i = 0; i < NBUF; i++)       // preload tiles NT-1, NT-2, NT-3
            issue_tile_tma(bufs[i], xb, NT - 1 - i, s2u(&mbar[i]));
    }

    float acc = 0.f;
    int par[NBUF] = {0, 0, 0};
    for (int i = 0; i < NT; i++) {
        const int t = NT - 1 - i;            // descending
        const int cur = i % NBUF;
        mbar_wait(s2u(&mbar[cur]), par[cur]);
        par[cur] ^= 1;

        const float* xt  = bufs[cur];
        const float* wst = ws + t * WT;
        #pragma unroll
        for (int w = 0; w < WT; w++)
            acc += wst[w] * xt[w * F_ + tid];
        __syncthreads();                     // all done reading cur

        if (i + NBUF < NT && tid == 0)
            issue_tile_tma(bufs[cur], xb, t - NBUF, s2u(&mbar[cur]));
    }
    g_t[b * F_ + tid] = acc;
}

// ---------------------------------------------------------------------------
// 32x32 tiled SGEMM, BK=32, 256 threads, 2x2 micro with LDS.64. (R8-proven)
// C = A[M,Kk] @ (TRANS_B ? Bm[Nn,Kk]^T : Bm[Kk,Nn]) * scale
// ---------------------------------------------------------------------------
template <int TRANS_B>
__global__ __launch_bounds__(256) void gemm32(const float* __restrict__ A,
                                              const float* __restrict__ Bm,
                                              float* __restrict__ C,
                                              int M, int Nn, int Kk, float scale) {
    __shared__ float As[32][36];
    __shared__ float Bs[32][36];
    const int tid = threadIdx.x;
    const int tx = tid & 15, ty = tid >> 4;
    const int m0 = blockIdx.y * 32, n0 = blockIdx.x * 32;
    float c00 = 0.f, c01 = 0.f, c10 = 0.f, c11 = 0.f;

    const int lm = tid >> 3, lk4 = tid & 7;

    for (int k0 = 0; k0 < Kk; k0 += 32) {
        {
            float4 v = *(const float4*)&A[(size_t)(m0 + lm) * Kk + k0 + lk4 * 4];
            As[lk4 * 4 + 0][lm] = v.x;
            As[lk4 * 4 + 1][lm] = v.y;
            As[lk4 * 4 + 2][lm] = v.z;
            As[lk4 * 4 + 3][lm] = v.w;
        }
        if (TRANS_B) {
            float4 v = *(const float4*)&Bm[(size_t)(n0 + lm) * Kk + k0 + lk4 * 4];
            Bs[lk4 * 4 + 0][lm] = v.x;
            Bs[lk4 * 4 + 1][lm] = v.y;
            Bs[lk4 * 4 + 2][lm] = v.z;
            Bs[lk4 * 4 + 3][lm] = v.w;
        } else {
            float4 v = *(const float4*)&Bm[(size_t)(k0 + lm) * Nn + n0 + lk4 * 4];
            Bs[lm][lk4 * 4 + 0] = v.x;
            Bs[lm][lk4 * 4 + 1] = v.y;
            Bs[lm][lk4 * 4 + 2] = v.z;
            Bs[lm][lk4 * 4 + 3] = v.w;
        }
        __syncthreads();
        #pragma unroll
        for (int k = 0; k < 32; k++) {
            const float2 a = *(const float2*)&As[k][ty * 2];
            const float2 b = *(const float2*)&Bs[k][tx * 2];
            c00 += a.x * b.x; c01 += a.x * b.y;
            c10 += a.y * b.x; c11 += a.y * b.y;
        }
        __syncthreads();
    }
    float* Cp = C + (size_t)(m0 + ty * 2) * Nn + n0 + tx * 2;
    Cp[0] = c00 * scale;  Cp[1] = c01 * scale;
    Cp[Nn] = c10 * scale; Cp[Nn + 1] = c11 * scale;
}

// ---------------------------------------------------------------------------
// Pass B: scores + online softmax + weighted accumulate. R8 compute skeleton,
// TMA 3-buffer pipeline for data movement.
// Dynamic smem: qks[512] | buf[3][WT*512]   (100352 B)
// ---------------------------------------------------------------------------
__global__ __launch_bounds__(512, 2) void k_attn(const float* __restrict__ x) {
    extern __shared__ float sm[];
    float* qks = sm;
    float* bufs[NBUF] = { sm + F_, sm + F_ + WT * F_, sm + F_ + 2 * WT * F_ };
    __shared__ float sc[WT];
    __shared__ float ps[WT];
    __shared__ alignas(8) unsigned long long mbar[NBUF];

    const int b = blockIdx.x, tid = threadIdx.x;
    const int wi = tid >> 5, lane = tid & 31;
    const char* xb = (const char*)(x + (size_t)b * W_ * F_);

    if (tid == 0) {
        #pragma unroll
        for (int i = 0; i < NBUF; i++) mbar_init(s2u(&mbar[i]), 1);
        fence_proxy_async_cta();
    }
    qks[tid] = g_qk[b * F_ + tid];
    __syncthreads();                         // init + qks visible

    if (tid == 0) {
        #pragma unroll
        for (int i = 0; i < NBUF; i++)       // preload tiles 0,1,2
            issue_tile_tma(bufs[i], xb, i, s2u(&mbar[i]));
    }

    float qkr[16];
    #pragma unroll
    for (int j = 0; j < 16; j++) qkr[j] = qks[lane + 32 * j];

    float m = -1e30f, s = 0.f, y = 0.f;
    int par[NBUF] = {0, 0, 0};

    for (int t = 0; t < NT; t++) {
        const int cur = t % NBUF;
        mbar_wait(s2u(&mbar[cur]), par[cur]);
        par[cur] ^= 1;

        const float* xt = bufs[cur];

        // Each warp: one word's dot product (qk already carries rsqrt(N))
        float d = 0.f;
        const float* xw = &xt[wi * F_];
        #pragma unroll
        for (int j = 0; j < 16; j++) d += xw[lane + 32 * j] * qkr[j];
        #pragma unroll
        for (int o = 16; o > 0; o >>= 1) d += __shfl_xor_sync(0xffffffffu, d, o);
        if (lane == 0) sc[wi] = d;
        __syncthreads();                     // sc ready

        // mn/corr uniform across threads; p[w] computed once by 16 threads
        float mn = m;
        #pragma unroll
        for (int w = 0; w < WT; w++) mn = fmaxf(mn, sc[w]);
        const float corr = __expf(m - mn);
        if (tid < WT) ps[tid] = __expf(sc[tid] - mn);
        m = mn;
        __syncthreads();                     // ps ready

        // Accumulate (thread owns f = tid)
        float pr[WT];
        #pragma unroll
        for (int w = 0; w < WT; w++) pr[w] = ps[w];
        float psum = 0.f;
        #pragma unroll
        for (int w = 0; w < WT; w++) psum += pr[w];
        s = s * corr + psum;
        y *= corr;
        #pragma unroll
        for (int w = 0; w < WT; w++) y += pr[w] * xt[w * F_ + tid];
        __syncthreads();                     // all done reading cur (+ sc/ps guard)

        if (t + NBUF < NT && tid == 0)
            issue_tile_tma(bufs[cur], xb, t + NBUF, s2u(&mbar[cur]));
    }
    g_y[b * F_ + tid] = y / s;
}

// ---------------------------------------------------------------------------
extern "C" void kernel_launch(void* const* d_in, const int* in_sizes, int n_in,
                              void* d_out, int out_size) {
    const float* x    = (const float*)d_in[0];
    const float* wk   = (const float*)d_in[1];
    const float* wq   = (const float*)d_in[2];
    const float* wv   = (const float*)d_in[3];
    const float* wvec = (const float*)d_in[4];
    float* out = (float*)d_out;

    float *pt, *pq, *pqk, *py;
    cudaGetSymbolAddress((void**)&pt,  g_t);
    cudaGetSymbolAddress((void**)&pq,  g_q);
    cudaGetSymbolAddress((void**)&pqk, g_qk);
    cudaGetSymbolAddress((void**)&py,  g_y);

    const int pipe_smem = (F_ + NBUF * WT * F_) * sizeof(float);   // 100352
    cudaFuncSetAttribute(k_t,    cudaFuncAttributeMaxDynamicSharedMemorySize, pipe_smem);
    cudaFuncSetAttribute(k_attn, cudaFuncAttributeMaxDynamicSharedMemorySize, pipe_smem);

    const float rsqrtN = 0.04419417382415922f;  // 1/sqrt(512)

    // Pass A over x: t
    k_t<<<B_, 512, pipe_smem>>>(x, wvec);
    // Q = t @ wq                 (256x512x512)
    gemm32<0><<<dim3(N_ / 32, B_ / 32), 256>>>(pt, wq, pq, B_, N_, F_, 1.f);
    // qk = (Q @ wk^T) * rsqrtN   (256x512x512)
    gemm32<1><<<dim3(F_ / 32, B_ / 32), 256>>>(pq, wk, pqk, B_, F_, N_, rsqrtN);
    // Pass B over x: attention
    k_attn<<<B_, 512, pipe_smem>>>(x);
    // out = y @ wv               (256x512x512)
    gemm32<0><<<dim3(N_ / 32, B_ / 32), 256>>>(py, wv, out, B_, N_, F_, 1.f);
}